// round 11
// baseline (speedup 1.0000x reference)
#include <cuda_runtime.h>
#include <cuda_fp16.h>
#include <math.h>
#include <cstdint>

#define N_NODES 50000
#define N_EDGES 800000
#define XWC     4224        // 4096 spline cols + 64 root cols + 64 pad
#define NSEG    8192        // NB * GRID^3
#define EPS_BN  1e-5f
#define NPASS   4
#define SRC_PER_PASS 12500  // N_NODES / NPASS

// ---------------- device scratch ----------------
__device__ __half g_xw[(long long)N_NODES * XWC];   // 422 MB fp16: x @ [W_k | root | 0]
__device__ __half g_xh[N_NODES * 64];               // x in fp16
__device__ __half g_wt[XWC * 64];                   // transposed weight [col][c] fp16
__device__ float g_agg[N_NODES * 64];
__device__ float g_cnt[N_NODES];
__device__ float g_stats[128];
__device__ float4 g_rec[N_EDGES];                   // t0,t1,t2, bits(src | base_k<<20)
__device__ int    g_rdst[N_EDGES];

// ---------------- helpers ----------------
__device__ __forceinline__ unsigned encf(float f) {
    unsigned u = __float_as_uint(f);
    return (u & 0x80000000u) ? ~u : (u | 0x80000000u);
}
__device__ __forceinline__ float decf(unsigned e) {
    return __uint_as_float((e & 0x80000000u) ? (e ^ 0x80000000u) : ~e);
}
__device__ __forceinline__ void red_add_v4(float* p, float a, float b, float c, float d) {
    asm volatile("red.global.add.v4.f32 [%0], {%1, %2, %3, %4};"
                 :: "l"(p), "f"(a), "f"(b), "f"(c), "f"(d) : "memory");
}
__device__ __forceinline__ void red_add_f32(float* p, float a) {
    asm volatile("red.global.add.f32 [%0], %1;" :: "l"(p), "f"(a) : "memory");
}
__device__ __forceinline__ void hmma16816(float* d, const uint32_t* a, const uint32_t* b) {
    asm volatile(
        "mma.sync.aligned.m16n8k16.row.col.f32.f16.f16.f32 "
        "{%0,%1,%2,%3}, {%4,%5,%6,%7}, {%8,%9}, {%0,%1,%2,%3};"
        : "+f"(d[0]), "+f"(d[1]), "+f"(d[2]), "+f"(d[3])
        : "r"(a[0]), "r"(a[1]), "r"(a[2]), "r"(a[3]), "r"(b[0]), "r"(b[1]));
}
__device__ __forceinline__ void ldsm_x4(uint32_t* r, uint32_t addr) {
    asm volatile("ldmatrix.sync.aligned.m8n8.x4.shared.b16 {%0,%1,%2,%3}, [%4];"
                 : "=r"(r[0]), "=r"(r[1]), "=r"(r[2]), "=r"(r[3]) : "r"(addr));
}
__device__ __forceinline__ uint32_t smem_u32(const void* p) {
    uint32_t a;
    asm("{ .reg .u64 t; cvta.to.shared.u64 t, %1; cvt.u32.u64 %0, t; }" : "=r"(a) : "l"(p));
    return a;
}
__device__ __forceinline__ void cp_async16(uint32_t dst, const void* src, int src_bytes) {
    asm volatile("cp.async.cg.shared.global [%0], [%1], 16, %2;"
                 :: "r"(dst), "l"(src), "r"(src_bytes) : "memory");
}
#define CP_COMMIT() asm volatile("cp.async.commit_group;" ::: "memory")
#define CP_WAIT0()  asm volatile("cp.async.wait_group 0;" ::: "memory")

// ---------------- prep: zeros + fp16 conversions + edge record precompute ----------
__global__ void prep_kernel(unsigned* __restrict__ out,
                            const float* __restrict__ x,
                            const float* __restrict__ w,
                            const float* __restrict__ root,
                            const int* __restrict__ eidx,
                            const float* __restrict__ attr) {
    int i = blockIdx.x * 256 + threadIdx.x;
    if (i < N_NODES * 64) {
        g_agg[i] = 0.f;
        g_xh[i] = __float2half_rn(x[i]);
    }
    if (i < N_NODES)   g_cnt[i] = 0.f;
    if (i < 128)       g_stats[i] = 0.f;
    if (i < NSEG * 64) out[i] = 0u;
    if (i < XWC * 64) {
        int col = i >> 6, c = i & 63;
        float v = 0.f;
        if (col < 4096) {
            int k = col >> 6, d = col & 63;
            v = w[k * 4096 + c * 64 + d];
        } else if (col < 4160) {
            v = root[c * 64 + (col - 4096)];
        }
        g_wt[i] = __float2half_rn(v);
    }
    if (i < N_EDGES) {
        int s = eidx[i];
        float f0 = attr[i * 3 + 0] * 3.f;
        float f1 = attr[i * 3 + 1] * 3.f;
        float f2 = attr[i * 3 + 2] * 3.f;
        float l0 = fminf(fmaxf(floorf(f0), 0.f), 2.f);
        float l1 = fminf(fmaxf(floorf(f1), 0.f), 2.f);
        float l2 = fminf(fmaxf(floorf(f2), 0.f), 2.f);
        int base_k = (int)l0 + 4 * (int)l1 + 16 * (int)l2;
        g_rec[i] = make_float4(f0 - l0, f1 - l1, f2 - l2,
                               __uint_as_float((unsigned)s | ((unsigned)base_k << 20)));
        g_rdst[i] = eidx[N_EDGES + i];
    }
}

// ---------------- HMMA GEMM: g_xw[m, col] = sum_c xh[m,c] * wt[col,c] ----------------
#define APAD 72   // halves per smem row
#define CPAD 136  // C staging stride in halves

__global__ void __launch_bounds__(256, 2) mm_kernel() {
    __shared__ __half sA[128 * APAD];
    __shared__ __half sB[128 * APAD];

    const int t = threadIdx.x;
    const int m0 = blockIdx.y * 128;
    const int col0 = blockIdx.x * 128;

    const uint32_t sAb = smem_u32(sA);
    const uint32_t sBb = smem_u32(sB);

    #pragma unroll
    for (int i = 0; i < 4; i++) {
        int f = t + i * 256;
        int m = f >> 3;
        int c8 = (f & 7) * 8;
        cp_async16(sAb + (m * APAD + c8) * 2,
                   g_xh + (long long)(m0 + m) * 64 + c8,
                   (m0 + m < N_NODES) ? 16 : 0);
    }
    #pragma unroll
    for (int i = 0; i < 4; i++) {
        int f = t + i * 256;
        int j = f >> 3;
        int c8 = (f & 7) * 8;
        cp_async16(sBb + (j * APAD + c8) * 2,
                   g_wt + (long long)(col0 + j) * 64 + c8, 16);
    }
    CP_COMMIT();
    CP_WAIT0();
    __syncthreads();

    const int warp = t >> 5, lane = t & 31;
    const int wm = (warp & 3) * 32;
    const int wn = (warp >> 2) * 64;
    const int g = lane >> 2, tg = lane & 3;

    const int a_row = lane & 15, a_kc = (lane >> 4) * 8;
    const int b_row = (lane & 7) + (lane >> 4) * 8;
    const int b_kc  = ((lane >> 3) & 1) * 8;

    float acc[2][8][4];
    #pragma unroll
    for (int mf = 0; mf < 2; mf++)
        #pragma unroll
        for (int nf = 0; nf < 8; nf++)
            #pragma unroll
            for (int q = 0; q < 4; q++) acc[mf][nf][q] = 0.f;

    #pragma unroll
    for (int ks = 0; ks < 4; ks++) {
        int k0 = ks * 16;
        uint32_t a[2][4];
        #pragma unroll
        for (int mf = 0; mf < 2; mf++)
            ldsm_x4(a[mf], sAb + ((wm + mf * 16 + a_row) * APAD + k0 + a_kc) * 2);
        uint32_t b[8][2];
        #pragma unroll
        for (int np = 0; np < 4; np++) {
            uint32_t br[4];
            ldsm_x4(br, sBb + ((wn + np * 16 + b_row) * APAD + k0 + b_kc) * 2);
            b[2 * np][0] = br[0]; b[2 * np][1] = br[1];
            b[2 * np + 1][0] = br[2]; b[2 * np + 1][1] = br[3];
        }
        #pragma unroll
        for (int nf = 0; nf < 8; nf++) {
            hmma16816(acc[0][nf], a[0], b[nf]);
            hmma16816(acc[1][nf], a[1], b[nf]);
        }
    }

    __syncthreads();
    __half* sC = sA;   // reuse: 128*136*2 = 34816 B
    #pragma unroll
    for (int mf = 0; mf < 2; mf++) {
        #pragma unroll
        for (int nf = 0; nf < 8; nf++) {
            int c = wn + nf * 8 + 2 * tg;
            __half2 lo = __floats2half2_rn(acc[mf][nf][0], acc[mf][nf][1]);
            __half2 hi = __floats2half2_rn(acc[mf][nf][2], acc[mf][nf][3]);
            *reinterpret_cast<__half2*>(sC + (wm + mf * 16 + g)     * CPAD + c) = lo;
            *reinterpret_cast<__half2*>(sC + (wm + mf * 16 + g + 8) * CPAD + c) = hi;
        }
    }
    __syncthreads();
    #pragma unroll
    for (int i = 0; i < 8; i++) {
        int f = t + i * 256;
        int row = f >> 4;
        int q8 = (f & 15) * 8;
        if (m0 + row < N_NODES) {
            uint4 v = *reinterpret_cast<const uint4*>(sC + row * CPAD + q8);
            *reinterpret_cast<uint4*>(g_xw + (long long)(m0 + row) * XWC + col0 + q8) = v;
        }
    }
}

// ---------------- edge kernel: 4 src-range passes (blockIdx.y = pass) ----------------
// Each pass touches a ~105 MB slice of g_xw that stays L2-resident, turning the
// 2nd access to each (src,k) row into an L2 hit instead of a DRAM miss.
__global__ void __launch_bounds__(256) edge_kernel() {
    int t = threadIdx.x;
    int g = t >> 3;
    int l = t & 7;
    int e = blockIdx.x * 32 + g;
    if (e >= N_EDGES) return;

    int lo = blockIdx.y * SRC_PER_PASS;

    float4 r = __ldcs(&g_rec[e]);          // streamed: don't pollute L2
    unsigned sp = __float_as_uint(r.w);
    int s = (int)(sp & 0xFFFFFu);
    if ((unsigned)(s - lo) >= (unsigned)SRC_PER_PASS) return;

    int base_k = sp >> 20;
    int d = __ldcs(&g_rdst[e]);
    float t0 = r.x, t1 = r.y, t2 = r.z;
    float s0 = 1.f - t0, s1 = 1.f - t1, s2 = 1.f - t2;

    const __half* bp = g_xw + (long long)s * XWC + base_k * 64 + l * 8;

    uint4 q[8];
    #pragma unroll
    for (int b = 0; b < 8; b++) {
        int b0 = b & 1, b1 = (b >> 1) & 1, b2 = (b >> 2) & 1;
        q[b] = *reinterpret_cast<const uint4*>(bp + (b0 + 4 * b1 + 16 * b2) * 64);
    }

    float acc[8] = {0.f, 0.f, 0.f, 0.f, 0.f, 0.f, 0.f, 0.f};
    #pragma unroll
    for (int b = 0; b < 8; b++) {
        int b0 = b & 1, b1 = (b >> 1) & 1, b2 = (b >> 2) & 1;
        float wgt = (b0 ? t0 : s0) * (b1 ? t1 : s1) * (b2 ? t2 : s2);
        const __half2* h = reinterpret_cast<const __half2*>(&q[b]);
        #pragma unroll
        for (int j = 0; j < 4; j++) {
            float2 f = __half22float2(h[j]);
            acc[2 * j]     += wgt * f.x;
            acc[2 * j + 1] += wgt * f.y;
        }
    }
    float* ap = g_agg + (long long)d * 64 + l * 8;
    red_add_v4(ap,     acc[0], acc[1], acc[2], acc[3]);
    red_add_v4(ap + 4, acc[4], acc[5], acc[6], acc[7]);
    if (l == 0) red_add_f32(&g_cnt[d], 1.f);
}

// ---------------- node kernel: h = ELU(agg/cnt + xroot + bias), stats, fused max-pool
__global__ void __launch_bounds__(256) node_kernel(const float* __restrict__ bias,
                                                   const float* __restrict__ pos,
                                                   const int* __restrict__ batch,
                                                   unsigned* __restrict__ outp) {
    __shared__ float sred[128];
    int t = threadIdx.x;
    if (t < 128) sred[t] = 0.f;
    __syncthreads();

    int lane = t & 31, warp = t >> 5;
    int gw = blockIdx.x * 8 + warp;
    int nw = gridDim.x * 8;
    int d0 = lane, d1 = lane + 32;
    float b0 = bias[d0], b1 = bias[d1];
    float su0 = 0.f, sq0 = 0.f, su1 = 0.f, sq1 = 0.f;

    for (int n = gw; n < N_NODES; n += nw) {
        float ic = 1.f / fmaxf(g_cnt[n], 1.f);
        long long off = (long long)n * 64;
        const __half* xr = g_xw + (long long)n * XWC + 4096;
        float a0 = g_agg[off + d0] * ic + b0 + __half2float(xr[d0]);
        float a1 = g_agg[off + d1] * ic + b1 + __half2float(xr[d1]);
        float h0 = a0 > 0.f ? a0 : expm1f(a0);
        float h1 = a1 > 0.f ? a1 : expm1f(a1);
        su0 += h0; sq0 += h0 * h0;
        su1 += h1; sq1 += h1 * h1;
        float p0 = pos[n * 3 + 0], p1 = pos[n * 3 + 1], p2 = pos[n * 3 + 2];
        int v0 = min(max((int)floorf(p0 * (1.f / 32.f)), 0), 7);
        int v1 = min(max((int)floorf(p1 * (1.f / 32.f)), 0), 7);
        int v2 = min(max((int)floorf(p2 * (1.f / 32.f)), 0), 7);
        int cl = batch[n] * 512 + v0 * 64 + v1 * 8 + v2;
        unsigned* op = outp + (long long)cl * 64;
        atomicMax(op + d0, encf(h0));
        atomicMax(op + d1, encf(h1));
    }
    atomicAdd(&sred[d0], su0);
    atomicAdd(&sred[d1], su1);
    atomicAdd(&sred[64 + d0], sq0);
    atomicAdd(&sred[64 + d1], sq1);
    __syncthreads();
    if (t < 128) atomicAdd(&g_stats[t], sred[t]);
}

// ---------------- decode: BN finalize inline + apply affine to pooled maxima ----------
__global__ void decode_kernel(float* __restrict__ out,
                              const float* __restrict__ gamma,
                              const float* __restrict__ beta) {
    __shared__ float ssc[64], ssh[64];
    int t = threadIdx.x;
    if (t < 64) {
        float mean = g_stats[t] * (1.f / N_NODES);
        float var  = g_stats[64 + t] * (1.f / N_NODES) - mean * mean;
        float inv  = rsqrtf(var + EPS_BN);
        float sc   = gamma[t] * inv;
        ssc[t] = sc;
        ssh[t] = beta[t] - mean * sc;
    }
    __syncthreads();
    int i = blockIdx.x * 256 + t;
    if (i < NSEG * 64) {
        int d = i & 63;
        unsigned u = reinterpret_cast<unsigned*>(out)[i];
        out[i] = u ? (ssc[d] * decf(u) + ssh[d]) : 0.f;
    }
}

// ---------------- launch ----------------
extern "C" void kernel_launch(void* const* d_in, const int* in_sizes, int n_in,
                              void* d_out, int out_size) {
    const float* x      = (const float*)d_in[0];
    const int*   eidx   = (const int*)  d_in[1];
    const float* attr   = (const float*)d_in[2];
    const float* pos    = (const float*)d_in[3];
    const int*   batch  = (const int*)  d_in[4];
    const float* weight = (const float*)d_in[5];
    const float* root   = (const float*)d_in[6];
    const float* bias   = (const float*)d_in[7];
    const float* gamma  = (const float*)d_in[8];
    const float* beta   = (const float*)d_in[9];

    prep_kernel<<<12500, 256>>>((unsigned*)d_out, x, weight, root, eidx, attr);

    dim3 gg(XWC / 128, (N_NODES + 127) / 128);   // 33 x 391 (col-fast: B tile stays hot in L2)
    mm_kernel<<<gg, 256>>>();

    dim3 ge(N_EDGES / 32, NPASS);
    edge_kernel<<<ge, 256>>>();

    node_kernel<<<800, 256>>>(bias, pos, batch, (unsigned*)d_out);
    decode_kernel<<<(NSEG * 64 + 255) / 256, 256>>>((float*)d_out, gamma, beta);
}

// round 12
// speedup vs baseline: 1.0374x; 1.0374x over previous
#include <cuda_runtime.h>
#include <cuda_fp16.h>
#include <math.h>
#include <cstdint>

#define N_NODES 50000
#define N_EDGES 800000
#define XWC     4224        // 4096 spline cols + 64 root cols + 64 pad
#define NSEG    8192        // NB * GRID^3
#define EPS_BN  1e-5f

// ---------------- device scratch ----------------
__device__ __half g_xw[(long long)N_NODES * XWC];   // 422 MB fp16: x @ [W_k | root | 0]
__device__ __half g_xh[N_NODES * 64];               // x in fp16
__device__ __half g_wt[XWC * 64];                   // transposed weight [col][c] fp16
__device__ float g_agg[N_NODES * 64];
__device__ float g_cnt[N_NODES];
__device__ float g_stats[128];

// ---------------- helpers ----------------
__device__ __forceinline__ unsigned encf(float f) {
    unsigned u = __float_as_uint(f);
    return (u & 0x80000000u) ? ~u : (u | 0x80000000u);
}
__device__ __forceinline__ float decf(unsigned e) {
    return __uint_as_float((e & 0x80000000u) ? (e ^ 0x80000000u) : ~e);
}
__device__ __forceinline__ void red_add_v4(float* p, float a, float b, float c, float d) {
    asm volatile("red.global.add.v4.f32 [%0], {%1, %2, %3, %4};"
                 :: "l"(p), "f"(a), "f"(b), "f"(c), "f"(d) : "memory");
}
__device__ __forceinline__ void red_add_f32(float* p, float a) {
    asm volatile("red.global.add.f32 [%0], %1;" :: "l"(p), "f"(a) : "memory");
}
__device__ __forceinline__ void hmma16816(float* d, const uint32_t* a, const uint32_t* b) {
    asm volatile(
        "mma.sync.aligned.m16n8k16.row.col.f32.f16.f16.f32 "
        "{%0,%1,%2,%3}, {%4,%5,%6,%7}, {%8,%9}, {%0,%1,%2,%3};"
        : "+f"(d[0]), "+f"(d[1]), "+f"(d[2]), "+f"(d[3])
        : "r"(a[0]), "r"(a[1]), "r"(a[2]), "r"(a[3]), "r"(b[0]), "r"(b[1]));
}
__device__ __forceinline__ void ldsm_x4(uint32_t* r, uint32_t addr) {
    asm volatile("ldmatrix.sync.aligned.m8n8.x4.shared.b16 {%0,%1,%2,%3}, [%4];"
                 : "=r"(r[0]), "=r"(r[1]), "=r"(r[2]), "=r"(r[3]) : "r"(addr));
}
__device__ __forceinline__ uint32_t smem_u32(const void* p) {
    uint32_t a;
    asm("{ .reg .u64 t; cvta.to.shared.u64 t, %1; cvt.u32.u64 %0, t; }" : "=r"(a) : "l"(p));
    return a;
}
__device__ __forceinline__ void cp_async16(uint32_t dst, const void* src, int src_bytes) {
    asm volatile("cp.async.cg.shared.global [%0], [%1], 16, %2;"
                 :: "r"(dst), "l"(src), "r"(src_bytes) : "memory");
}
#define CP_COMMIT() asm volatile("cp.async.commit_group;" ::: "memory")
#define CP_WAIT0()  asm volatile("cp.async.wait_group 0;" ::: "memory")

// ---------------- prep: zeros + fp16 conversions (one launch) ----------
__global__ void prep_kernel(unsigned* __restrict__ out,
                            const float* __restrict__ x,
                            const float* __restrict__ w,
                            const float* __restrict__ root) {
    int i = blockIdx.x * 256 + threadIdx.x;
    if (i < N_NODES * 64) {
        g_agg[i] = 0.f;
        g_xh[i] = __float2half_rn(x[i]);
    }
    if (i < N_NODES)   g_cnt[i] = 0.f;
    if (i < 128)       g_stats[i] = 0.f;
    if (i < NSEG * 64) out[i] = 0u;
    if (i < XWC * 64) {
        int col = i >> 6, c = i & 63;
        float v = 0.f;
        if (col < 4096) {
            int k = col >> 6, d = col & 63;
            v = w[k * 4096 + c * 64 + d];
        } else if (col < 4160) {
            v = root[c * 64 + (col - 4096)];
        }
        g_wt[i] = __float2half_rn(v);
    }
}

// ---------------- HMMA GEMM: g_xw[m, col] = sum_c xh[m,c] * wt[col,c] ----------------
// Block 128x128, 8 warps 4Mx2N, warp tile 32x64. Direct fragment->global stores
// (no C smem staging: lanes tg=0..3 cover 16B-contiguous col segments).
#define APAD 72   // halves per smem row

__global__ void __launch_bounds__(256, 2) mm_kernel() {
    __shared__ __half sA[128 * APAD];
    __shared__ __half sB[128 * APAD];

    const int t = threadIdx.x;
    const int m0 = blockIdx.y * 128;
    const int col0 = blockIdx.x * 128;

    const uint32_t sAb = smem_u32(sA);
    const uint32_t sBb = smem_u32(sB);

    #pragma unroll
    for (int i = 0; i < 4; i++) {
        int f = t + i * 256;
        int m = f >> 3;
        int c8 = (f & 7) * 8;
        cp_async16(sAb + (m * APAD + c8) * 2,
                   g_xh + (long long)(m0 + m) * 64 + c8,
                   (m0 + m < N_NODES) ? 16 : 0);
    }
    #pragma unroll
    for (int i = 0; i < 4; i++) {
        int f = t + i * 256;
        int j = f >> 3;
        int c8 = (f & 7) * 8;
        cp_async16(sBb + (j * APAD + c8) * 2,
                   g_wt + (long long)(col0 + j) * 64 + c8, 16);
    }
    CP_COMMIT();
    CP_WAIT0();
    __syncthreads();

    const int warp = t >> 5, lane = t & 31;
    const int wm = (warp & 3) * 32;
    const int wn = (warp >> 2) * 64;
    const int g = lane >> 2, tg = lane & 3;

    const int a_row = lane & 15, a_kc = (lane >> 4) * 8;
    const int b_row = (lane & 7) + (lane >> 4) * 8;
    const int b_kc  = ((lane >> 3) & 1) * 8;

    float acc[2][8][4];
    #pragma unroll
    for (int mf = 0; mf < 2; mf++)
        #pragma unroll
        for (int nf = 0; nf < 8; nf++)
            #pragma unroll
            for (int q = 0; q < 4; q++) acc[mf][nf][q] = 0.f;

    #pragma unroll
    for (int ks = 0; ks < 4; ks++) {
        int k0 = ks * 16;
        uint32_t a[2][4];
        #pragma unroll
        for (int mf = 0; mf < 2; mf++)
            ldsm_x4(a[mf], sAb + ((wm + mf * 16 + a_row) * APAD + k0 + a_kc) * 2);
        uint32_t b[8][2];
        #pragma unroll
        for (int np = 0; np < 4; np++) {
            uint32_t br[4];
            ldsm_x4(br, sBb + ((wn + np * 16 + b_row) * APAD + k0 + b_kc) * 2);
            b[2 * np][0] = br[0]; b[2 * np][1] = br[1];
            b[2 * np + 1][0] = br[2]; b[2 * np + 1][1] = br[3];
        }
        #pragma unroll
        for (int nf = 0; nf < 8; nf++) {
            hmma16816(acc[0][nf], a[0], b[nf]);
            hmma16816(acc[1][nf], a[1], b[nf]);
        }
    }

    // direct fragment -> global stores (fp16), no smem staging
    #pragma unroll
    for (int mf = 0; mf < 2; mf++) {
        int r0 = m0 + wm + mf * 16 + g;
        __half* p0 = g_xw + (long long)r0 * XWC + col0 + wn + 2 * tg;
        __half* p1 = p0 + (long long)8 * XWC;
        bool ok0 = r0 < N_NODES;
        bool ok1 = (r0 + 8) < N_NODES;
        #pragma unroll
        for (int nf = 0; nf < 8; nf++) {
            __half2 lo = __floats2half2_rn(acc[mf][nf][0], acc[mf][nf][1]);
            __half2 hi = __floats2half2_rn(acc[mf][nf][2], acc[mf][nf][3]);
            if (ok0) *reinterpret_cast<__half2*>(p0 + nf * 8) = lo;
            if (ok1) *reinterpret_cast<__half2*>(p1 + nf * 8) = hi;
        }
    }
}

// ---------------- edge kernel: spline-weighted gather + scatter-add (R10 version) ----
__global__ void __launch_bounds__(256) edge_kernel(const int* __restrict__ eidx,
                                                   const float* __restrict__ attr) {
    int t = threadIdx.x;
    int g = t >> 3;
    int l = t & 7;
    int e = blockIdx.x * 32 + g;
    if (e >= N_EDGES) return;

    int s = eidx[e];
    int d = eidx[N_EDGES + e];

    float f0 = attr[e * 3 + 0] * 3.f;
    float f1 = attr[e * 3 + 1] * 3.f;
    float f2 = attr[e * 3 + 2] * 3.f;
    float l0 = fminf(fmaxf(floorf(f0), 0.f), 2.f);
    float l1 = fminf(fmaxf(floorf(f1), 0.f), 2.f);
    float l2 = fminf(fmaxf(floorf(f2), 0.f), 2.f);
    float t0 = f0 - l0, t1 = f1 - l1, t2 = f2 - l2;
    float s0 = 1.f - t0, s1 = 1.f - t1, s2 = 1.f - t2;
    int base_k = (int)l0 + 4 * (int)l1 + 16 * (int)l2;

    const __half* bp = g_xw + (long long)s * XWC + base_k * 64 + l * 8;

    uint4 q[8];
    #pragma unroll
    for (int b = 0; b < 8; b++) {
        int b0 = b & 1, b1 = (b >> 1) & 1, b2 = (b >> 2) & 1;
        q[b] = *reinterpret_cast<const uint4*>(bp + (b0 + 4 * b1 + 16 * b2) * 64);
    }

    float acc[8] = {0.f, 0.f, 0.f, 0.f, 0.f, 0.f, 0.f, 0.f};
    #pragma unroll
    for (int b = 0; b < 8; b++) {
        int b0 = b & 1, b1 = (b >> 1) & 1, b2 = (b >> 2) & 1;
        float wgt = (b0 ? t0 : s0) * (b1 ? t1 : s1) * (b2 ? t2 : s2);
        const __half2* h = reinterpret_cast<const __half2*>(&q[b]);
        #pragma unroll
        for (int j = 0; j < 4; j++) {
            float2 f = __half22float2(h[j]);
            acc[2 * j]     += wgt * f.x;
            acc[2 * j + 1] += wgt * f.y;
        }
    }
    float* ap = g_agg + (long long)d * 64 + l * 8;
    red_add_v4(ap,     acc[0], acc[1], acc[2], acc[3]);
    red_add_v4(ap + 4, acc[4], acc[5], acc[6], acc[7]);
    if (l == 0) red_add_f32(&g_cnt[d], 1.f);
}

// ---------------- node kernel: h = ELU(agg/cnt + xroot + bias), stats, fused max-pool
__global__ void __launch_bounds__(256) node_kernel(const float* __restrict__ bias,
                                                   const float* __restrict__ pos,
                                                   const int* __restrict__ batch,
                                                   unsigned* __restrict__ outp) {
    __shared__ float sred[128];
    int t = threadIdx.x;
    if (t < 128) sred[t] = 0.f;
    __syncthreads();

    int lane = t & 31, warp = t >> 5;
    int gw = blockIdx.x * 8 + warp;
    int nw = gridDim.x * 8;
    int d0 = lane, d1 = lane + 32;
    float b0 = bias[d0], b1 = bias[d1];
    float su0 = 0.f, sq0 = 0.f, su1 = 0.f, sq1 = 0.f;

    for (int n = gw; n < N_NODES; n += nw) {
        float ic = 1.f / fmaxf(g_cnt[n], 1.f);
        long long off = (long long)n * 64;
        const __half* xr = g_xw + (long long)n * XWC + 4096;
        float a0 = g_agg[off + d0] * ic + b0 + __half2float(xr[d0]);
        float a1 = g_agg[off + d1] * ic + b1 + __half2float(xr[d1]);
        float h0 = a0 > 0.f ? a0 : expm1f(a0);
        float h1 = a1 > 0.f ? a1 : expm1f(a1);
        su0 += h0; sq0 += h0 * h0;
        su1 += h1; sq1 += h1 * h1;
        float p0 = pos[n * 3 + 0], p1 = pos[n * 3 + 1], p2 = pos[n * 3 + 2];
        int v0 = min(max((int)floorf(p0 * (1.f / 32.f)), 0), 7);
        int v1 = min(max((int)floorf(p1 * (1.f / 32.f)), 0), 7);
        int v2 = min(max((int)floorf(p2 * (1.f / 32.f)), 0), 7);
        int cl = batch[n] * 512 + v0 * 64 + v1 * 8 + v2;
        unsigned* op = outp + (long long)cl * 64;
        atomicMax(op + d0, encf(h0));
        atomicMax(op + d1, encf(h1));
    }
    atomicAdd(&sred[d0], su0);
    atomicAdd(&sred[d1], su1);
    atomicAdd(&sred[64 + d0], sq0);
    atomicAdd(&sred[64 + d1], sq1);
    __syncthreads();
    if (t < 128) atomicAdd(&g_stats[t], sred[t]);
}

// ---------------- decode: BN finalize inline + apply affine to pooled maxima ----------
__global__ void decode_kernel(float* __restrict__ out,
                              const float* __restrict__ gamma,
                              const float* __restrict__ beta) {
    __shared__ float ssc[64], ssh[64];
    int t = threadIdx.x;
    if (t < 64) {
        float mean = g_stats[t] * (1.f / N_NODES);
        float var  = g_stats[64 + t] * (1.f / N_NODES) - mean * mean;
        float inv  = rsqrtf(var + EPS_BN);
        float sc   = gamma[t] * inv;
        ssc[t] = sc;
        ssh[t] = beta[t] - mean * sc;
    }
    __syncthreads();
    int i = blockIdx.x * 256 + t;
    if (i < NSEG * 64) {
        int d = i & 63;
        unsigned u = reinterpret_cast<unsigned*>(out)[i];
        out[i] = u ? (ssc[d] * decf(u) + ssh[d]) : 0.f;
    }
}

// ---------------- launch ----------------
extern "C" void kernel_launch(void* const* d_in, const int* in_sizes, int n_in,
                              void* d_out, int out_size) {
    const float* x      = (const float*)d_in[0];
    const int*   eidx   = (const int*)  d_in[1];
    const float* attr   = (const float*)d_in[2];
    const float* pos    = (const float*)d_in[3];
    const int*   batch  = (const int*)  d_in[4];
    const float* weight = (const float*)d_in[5];
    const float* root   = (const float*)d_in[6];
    const float* bias   = (const float*)d_in[7];
    const float* gamma  = (const float*)d_in[8];
    const float* beta   = (const float*)d_in[9];

    prep_kernel<<<12500, 256>>>((unsigned*)d_out, x, weight, root);

    dim3 gg(XWC / 128, (N_NODES + 127) / 128);   // 33 x 391 (col-fast: B tile stays hot in L2)
    mm_kernel<<<gg, 256>>>();

    edge_kernel<<<N_EDGES / 32, 256>>>(eidx, attr);
    node_kernel<<<800, 256>>>(bias, pos, batch, (unsigned*)d_out);
    decode_kernel<<<(NSEG * 64 + 255) / 256, 256>>>((float*)d_out, gamma, beta);
}

// round 13
// speedup vs baseline: 1.2399x; 1.1951x over previous
#include <cuda_runtime.h>
#include <cuda_fp16.h>
#include <math.h>
#include <cstdint>

#define N_NODES 50000
#define N_EDGES 800000
#define XWC     4224        // 4096 spline cols + 64 root cols + 64 pad
#define XWC_USED 4160       // columns actually written/read
#define NSEG    8192        // NB * GRID^3
#define EPS_BN  1e-5f

// ---------------- device scratch ----------------
__device__ __half g_xw[(long long)N_NODES * XWC];   // 422 MB fp16: x @ [W_k | root | 0]
__device__ __half g_xh[N_NODES * 64];               // x in fp16
__device__ __half g_wt[XWC * 64];                   // transposed weight [col][c] fp16
__device__ float g_agg[N_NODES * 64];
__device__ float g_cnt[N_NODES];
__device__ float g_stats[128];

// ---------------- helpers ----------------
__device__ __forceinline__ unsigned encf(float f) {
    unsigned u = __float_as_uint(f);
    return (u & 0x80000000u) ? ~u : (u | 0x80000000u);
}
__device__ __forceinline__ float decf(unsigned e) {
    return __uint_as_float((e & 0x80000000u) ? (e ^ 0x80000000u) : ~e);
}
__device__ __forceinline__ void red_add_v4(float* p, float a, float b, float c, float d) {
    asm volatile("red.global.add.v4.f32 [%0], {%1, %2, %3, %4};"
                 :: "l"(p), "f"(a), "f"(b), "f"(c), "f"(d) : "memory");
}
__device__ __forceinline__ void red_add_f32(float* p, float a) {
    asm volatile("red.global.add.f32 [%0], %1;" :: "l"(p), "f"(a) : "memory");
}
__device__ __forceinline__ void hmma16816(float* d, const uint32_t* a, const uint32_t* b) {
    asm volatile(
        "mma.sync.aligned.m16n8k16.row.col.f32.f16.f16.f32 "
        "{%0,%1,%2,%3}, {%4,%5,%6,%7}, {%8,%9}, {%0,%1,%2,%3};"
        : "+f"(d[0]), "+f"(d[1]), "+f"(d[2]), "+f"(d[3])
        : "r"(a[0]), "r"(a[1]), "r"(a[2]), "r"(a[3]), "r"(b[0]), "r"(b[1]));
}
__device__ __forceinline__ void ldsm_x4(uint32_t* r, uint32_t addr) {
    asm volatile("ldmatrix.sync.aligned.m8n8.x4.shared.b16 {%0,%1,%2,%3}, [%4];"
                 : "=r"(r[0]), "=r"(r[1]), "=r"(r[2]), "=r"(r[3]) : "r"(addr));
}
__device__ __forceinline__ uint32_t smem_u32(const void* p) {
    uint32_t a;
    asm("{ .reg .u64 t; cvta.to.shared.u64 t, %1; cvt.u32.u64 %0, t; }" : "=r"(a) : "l"(p));
    return a;
}
__device__ __forceinline__ void cp_async16(uint32_t dst, const void* src, int src_bytes) {
    asm volatile("cp.async.cg.shared.global [%0], [%1], 16, %2;"
                 :: "r"(dst), "l"(src), "r"(src_bytes) : "memory");
}
#define CP_COMMIT() asm volatile("cp.async.commit_group;" ::: "memory")
#define CP_WAIT0()  asm volatile("cp.async.wait_group 0;" ::: "memory")

// ---------------- prep: zeros + fp16 conversions + degree counts (one launch) -------
__global__ void prep_kernel(unsigned* __restrict__ out,
                            const float* __restrict__ x,
                            const float* __restrict__ w,
                            const float* __restrict__ root,
                            const int* __restrict__ eidx) {
    int i = blockIdx.x * 256 + threadIdx.x;
    if (i < N_NODES * 64) {
        g_agg[i] = 0.f;
        g_xh[i] = __float2half_rn(x[i]);
    }
    if (i < N_NODES)   g_cnt[i] = 0.f;
    if (i < 128)       g_stats[i] = 0.f;
    if (i < NSEG * 64) out[i] = 0u;
    if (i < XWC * 64) {
        int col = i >> 6, c = i & 63;
        float v = 0.f;
        if (col < 4096) {
            int k = col >> 6, d = col & 63;
            v = w[k * 4096 + c * 64 + d];
        } else if (col < 4160) {
            v = root[c * 64 + (col - 4096)];
        }
        g_wt[i] = __float2half_rn(v);
    }
}
// separate tiny kernel: degree counts (needs g_cnt zeroed first)
__global__ void cnt_kernel(const int* __restrict__ eidx) {
    int e = blockIdx.x * 256 + threadIdx.x;
    if (e < N_EDGES) red_add_f32(&g_cnt[eidx[N_EDGES + e]], 1.f);
}

// ---------------- HMMA GEMM: g_xw[m, col] = sum_c xh[m,c] * wt[col,c] ----------------
// Block tile 128(M) x 128(N), 8 warps as 4M x 2N, warp tile 32x64, cp.async inputs.
#define APAD 72   // halves per smem row (144 B, 16B-aligned)
#define CPAD 136  // C staging stride in halves

__global__ void __launch_bounds__(256, 2) mm_kernel() {
    __shared__ __half sA[128 * APAD];
    __shared__ __half sB[128 * APAD];

    const int t = threadIdx.x;
    const int m0 = blockIdx.y * 128;
    const int col0 = blockIdx.x * 128;

    const uint32_t sAb = smem_u32(sA);
    const uint32_t sBb = smem_u32(sB);

    #pragma unroll
    for (int i = 0; i < 4; i++) {
        int f = t + i * 256;
        int m = f >> 3;
        int c8 = (f & 7) * 8;
        cp_async16(sAb + (m * APAD + c8) * 2,
                   g_xh + (long long)(m0 + m) * 64 + c8,
                   (m0 + m < N_NODES) ? 16 : 0);
    }
    #pragma unroll
    for (int i = 0; i < 4; i++) {
        int f = t + i * 256;
        int j = f >> 3;
        int c8 = (f & 7) * 8;
        cp_async16(sBb + (j * APAD + c8) * 2,
                   g_wt + (long long)(col0 + j) * 64 + c8, 16);
    }
    CP_COMMIT();
    CP_WAIT0();
    __syncthreads();

    const int warp = t >> 5, lane = t & 31;
    const int wm = (warp & 3) * 32;
    const int wn = (warp >> 2) * 64;
    const int g = lane >> 2, tg = lane & 3;

    const int a_row = lane & 15, a_kc = (lane >> 4) * 8;
    const int b_row = (lane & 7) + (lane >> 4) * 8;
    const int b_kc  = ((lane >> 3) & 1) * 8;

    float acc[2][8][4];
    #pragma unroll
    for (int mf = 0; mf < 2; mf++)
        #pragma unroll
        for (int nf = 0; nf < 8; nf++)
            #pragma unroll
            for (int q = 0; q < 4; q++) acc[mf][nf][q] = 0.f;

    #pragma unroll
    for (int ks = 0; ks < 4; ks++) {
        int k0 = ks * 16;
        uint32_t a[2][4];
        #pragma unroll
        for (int mf = 0; mf < 2; mf++)
            ldsm_x4(a[mf], sAb + ((wm + mf * 16 + a_row) * APAD + k0 + a_kc) * 2);
        uint32_t b[8][2];
        #pragma unroll
        for (int np = 0; np < 4; np++) {
            uint32_t br[4];
            ldsm_x4(br, sBb + ((wn + np * 16 + b_row) * APAD + k0 + b_kc) * 2);
            b[2 * np][0] = br[0]; b[2 * np][1] = br[1];
            b[2 * np + 1][0] = br[2]; b[2 * np + 1][1] = br[3];
        }
        #pragma unroll
        for (int nf = 0; nf < 8; nf++) {
            hmma16816(acc[0][nf], a[0], b[nf]);
            hmma16816(acc[1][nf], a[1], b[nf]);
        }
    }

    __syncthreads();
    __half* sC = sA;   // reuse: 128*136*2 = 34816 B
    #pragma unroll
    for (int mf = 0; mf < 2; mf++) {
        #pragma unroll
        for (int nf = 0; nf < 8; nf++) {
            int c = wn + nf * 8 + 2 * tg;
            __half2 lo = __floats2half2_rn(acc[mf][nf][0], acc[mf][nf][1]);
            __half2 hi = __floats2half2_rn(acc[mf][nf][2], acc[mf][nf][3]);
            *reinterpret_cast<__half2*>(sC + (wm + mf * 16 + g)     * CPAD + c) = lo;
            *reinterpret_cast<__half2*>(sC + (wm + mf * 16 + g + 8) * CPAD + c) = hi;
        }
    }
    __syncthreads();
    #pragma unroll
    for (int i = 0; i < 8; i++) {
        int f = t + i * 256;
        int row = f >> 4;
        int q8 = (f & 15) * 8;
        if (m0 + row < N_NODES && col0 + q8 < XWC_USED) {   // skip zero pad columns
            uint4 v = *reinterpret_cast<const uint4*>(sC + row * CPAD + q8);
            *reinterpret_cast<uint4*>(g_xw + (long long)(m0 + row) * XWC + col0 + q8) = v;
        }
    }
}

// ---------------- edge kernel: spline-weighted gather + scatter-add ----------------
__global__ void __launch_bounds__(256) edge_kernel(const int* __restrict__ eidx,
                                                   const float* __restrict__ attr) {
    int t = threadIdx.x;
    int g = t >> 3;
    int l = t & 7;
    int e = blockIdx.x * 32 + g;
    if (e >= N_EDGES) return;

    int s = eidx[e];
    int d = eidx[N_EDGES + e];

    float f0 = attr[e * 3 + 0] * 3.f;
    float f1 = attr[e * 3 + 1] * 3.f;
    float f2 = attr[e * 3 + 2] * 3.f;
    float l0 = fminf(fmaxf(floorf(f0), 0.f), 2.f);
    float l1 = fminf(fmaxf(floorf(f1), 0.f), 2.f);
    float l2 = fminf(fmaxf(floorf(f2), 0.f), 2.f);
    float t0 = f0 - l0, t1 = f1 - l1, t2 = f2 - l2;
    float s0 = 1.f - t0, s1 = 1.f - t1, s2 = 1.f - t2;
    int base_k = (int)l0 + 4 * (int)l1 + 16 * (int)l2;

    const __half* bp = g_xw + (long long)s * XWC + base_k * 64 + l * 8;

    uint4 q[8];
    #pragma unroll
    for (int b = 0; b < 8; b++) {
        int b0 = b & 1, b1 = (b >> 1) & 1, b2 = (b >> 2) & 1;
        q[b] = *reinterpret_cast<const uint4*>(bp + (b0 + 4 * b1 + 16 * b2) * 64);
    }

    float acc[8] = {0.f, 0.f, 0.f, 0.f, 0.f, 0.f, 0.f, 0.f};
    #pragma unroll
    for (int b = 0; b < 8; b++) {
        int b0 = b & 1, b1 = (b >> 1) & 1, b2 = (b >> 2) & 1;
        float wgt = (b0 ? t0 : s0) * (b1 ? t1 : s1) * (b2 ? t2 : s2);
        const __half2* h = reinterpret_cast<const __half2*>(&q[b]);
        #pragma unroll
        for (int j = 0; j < 4; j++) {
            float2 f = __half22float2(h[j]);
            acc[2 * j]     += wgt * f.x;
            acc[2 * j + 1] += wgt * f.y;
        }
    }
    float* ap = g_agg + (long long)d * 64 + l * 8;
    red_add_v4(ap,     acc[0], acc[1], acc[2], acc[3]);
    red_add_v4(ap + 4, acc[4], acc[5], acc[6], acc[7]);
}

// ---------------- node kernel: h = ELU(agg/cnt + xroot + bias), stats, fused max-pool
__global__ void __launch_bounds__(256) node_kernel(const float* __restrict__ bias,
                                                   const float* __restrict__ pos,
                                                   const int* __restrict__ batch,
                                                   unsigned* __restrict__ outp) {
    __shared__ float sred[128];
    int t = threadIdx.x;
    if (t < 128) sred[t] = 0.f;
    __syncthreads();

    int lane = t & 31, warp = t >> 5;
    int gw = blockIdx.x * 8 + warp;
    int nw = gridDim.x * 8;
    int d0 = lane, d1 = lane + 32;
    float b0 = bias[d0], b1 = bias[d1];
    float su0 = 0.f, sq0 = 0.f, su1 = 0.f, sq1 = 0.f;

    for (int n = gw; n < N_NODES; n += nw) {
        float ic = 1.f / fmaxf(g_cnt[n], 1.f);
        long long off = (long long)n * 64;
        const __half* xr = g_xw + (long long)n * XWC + 4096;
        float a0 = g_agg[off + d0] * ic + b0 + __half2float(xr[d0]);
        float a1 = g_agg[off + d1] * ic + b1 + __half2float(xr[d1]);
        float h0 = a0 > 0.f ? a0 : expm1f(a0);
        float h1 = a1 > 0.f ? a1 : expm1f(a1);
        su0 += h0; sq0 += h0 * h0;
        su1 += h1; sq1 += h1 * h1;
        float p0 = pos[n * 3 + 0], p1 = pos[n * 3 + 1], p2 = pos[n * 3 + 2];
        int v0 = min(max((int)floorf(p0 * (1.f / 32.f)), 0), 7);
        int v1 = min(max((int)floorf(p1 * (1.f / 32.f)), 0), 7);
        int v2 = min(max((int)floorf(p2 * (1.f / 32.f)), 0), 7);
        int cl = batch[n] * 512 + v0 * 64 + v1 * 8 + v2;
        unsigned* op = outp + (long long)cl * 64;
        atomicMax(op + d0, encf(h0));
        atomicMax(op + d1, encf(h1));
    }
    atomicAdd(&sred[d0], su0);
    atomicAdd(&sred[d1], su1);
    atomicAdd(&sred[64 + d0], sq0);
    atomicAdd(&sred[64 + d1], sq1);
    __syncthreads();
    if (t < 128) atomicAdd(&g_stats[t], sred[t]);
}

// ---------------- decode: BN finalize inline + apply affine to pooled maxima ----------
__global__ void decode_kernel(float* __restrict__ out,
                              const float* __restrict__ gamma,
                              const float* __restrict__ beta) {
    __shared__ float ssc[64], ssh[64];
    int t = threadIdx.x;
    if (t < 64) {
        float mean = g_stats[t] * (1.f / N_NODES);
        float var  = g_stats[64 + t] * (1.f / N_NODES) - mean * mean;
        float inv  = rsqrtf(var + EPS_BN);
        float sc   = gamma[t] * inv;
        ssc[t] = sc;
        ssh[t] = beta[t] - mean * sc;
    }
    __syncthreads();
    int i = blockIdx.x * 256 + t;
    if (i < NSEG * 64) {
        int d = i & 63;
        unsigned u = reinterpret_cast<unsigned*>(out)[i];
        out[i] = u ? (ssc[d] * decf(u) + ssh[d]) : 0.f;
    }
}

// ---------------- launch ----------------
extern "C" void kernel_launch(void* const* d_in, const int* in_sizes, int n_in,
                              void* d_out, int out_size) {
    const float* x      = (const float*)d_in[0];
    const int*   eidx   = (const int*)  d_in[1];
    const float* attr   = (const float*)d_in[2];
    const float* pos    = (const float*)d_in[3];
    const int*   batch  = (const int*)  d_in[4];
    const float* weight = (const float*)d_in[5];
    const float* root   = (const float*)d_in[6];
    const float* bias   = (const float*)d_in[7];
    const float* gamma  = (const float*)d_in[8];
    const float* beta   = (const float*)d_in[9];

    prep_kernel<<<12500, 256>>>((unsigned*)d_out, x, weight, root, eidx);
    cnt_kernel<<<(N_EDGES + 255) / 256, 256>>>(eidx);

    dim3 gg(XWC / 128, (N_NODES + 127) / 128);   // 33 x 391 (col-fast: B tile stays hot in L2)
    mm_kernel<<<gg, 256>>>();

    edge_kernel<<<N_EDGES / 32, 256>>>(eidx, attr);
    node_kernel<<<800, 256>>>(bias, pos, batch, (unsigned*)d_out);
    decode_kernel<<<(NSEG * 64 + 255) / 256, 256>>>((float*)d_out, gamma, beta);
}

// round 14
// speedup vs baseline: 1.5701x; 1.2663x over previous
#include <cuda_runtime.h>
#include <cuda_fp16.h>
#include <math.h>
#include <cstdint>

#define N_NODES 50000
#define N_EDGES 800000
#define NGRP    27
#define PADE    (N_EDGES + NGRP * 128)   // 803456
#define NBLK    (PADE / 128)             // 6277
#define WTC     4160                     // 4096 spline cols + 64 root cols
#define NSEG    8192
#define EPS_BN  1e-5f

// ---------------- device scratch ----------------
__device__ __half g_xh[N_NODES * 64];            // x fp16
__device__ __half g_wt[WTC * 64];                // [col][cin] fp16 (spline + root)
__device__ float  g_xr[N_NODES * 64];            // x @ root (fp32)
__device__ float  g_agg[(N_NODES + 1) * 64];     // +1 dump row for pad edges
__device__ float  g_cnt[N_NODES];
__device__ float  g_stats[128];
__device__ float4 g_rec[PADE];                   // t0,t1,t2, bits(src)
__device__ int    g_rdst[PADE];
__device__ int    g_bcnt[32];
__device__ int    g_boff[32];                    // padded exclusive offsets, [27]=total
__device__ int    g_bfill[32];

// ---------------- helpers ----------------
__device__ __forceinline__ unsigned encf(float f) {
    unsigned u = __float_as_uint(f);
    return (u & 0x80000000u) ? ~u : (u | 0x80000000u);
}
__device__ __forceinline__ float decf(unsigned e) {
    return __uint_as_float((e & 0x80000000u) ? (e ^ 0x80000000u) : ~e);
}
__device__ __forceinline__ void red_add_v4(float* p, float a, float b, float c, float d) {
    asm volatile("red.global.add.v4.f32 [%0], {%1, %2, %3, %4};"
                 :: "l"(p), "f"(a), "f"(b), "f"(c), "f"(d) : "memory");
}
__device__ __forceinline__ void red_add_f32(float* p, float a) {
    asm volatile("red.global.add.f32 [%0], %1;" :: "l"(p), "f"(a) : "memory");
}
__device__ __forceinline__ void hmma16816(float* d, const uint32_t* a, const uint32_t* b) {
    asm volatile(
        "mma.sync.aligned.m16n8k16.row.col.f32.f16.f16.f32 "
        "{%0,%1,%2,%3}, {%4,%5,%6,%7}, {%8,%9}, {%0,%1,%2,%3};"
        : "+f"(d[0]), "+f"(d[1]), "+f"(d[2]), "+f"(d[3])
        : "r"(a[0]), "r"(a[1]), "r"(a[2]), "r"(a[3]), "r"(b[0]), "r"(b[1]));
}
__device__ __forceinline__ void ldsm_x4(uint32_t* r, uint32_t addr) {
    asm volatile("ldmatrix.sync.aligned.m8n8.x4.shared.b16 {%0,%1,%2,%3}, [%4];"
                 : "=r"(r[0]), "=r"(r[1]), "=r"(r[2]), "=r"(r[3]) : "r"(addr));
}
__device__ __forceinline__ uint32_t smem_u32(const void* p) {
    uint32_t a;
    asm("{ .reg .u64 t; cvta.to.shared.u64 t, %1; cvt.u32.u64 %0, t; }" : "=r"(a) : "l"(p));
    return a;
}
__device__ __forceinline__ void cp_async16(uint32_t dst, const void* src, int src_bytes) {
    asm volatile("cp.async.cg.shared.global [%0], [%1], 16, %2;"
                 :: "r"(dst), "l"(src), "r"(src_bytes) : "memory");
}
#define CP_COMMIT() asm volatile("cp.async.commit_group;" ::: "memory")
#define CP_WAIT0()  asm volatile("cp.async.wait_group 0;" ::: "memory")
__device__ __forceinline__ uint32_t hmul2u(uint32_t a, uint32_t b) {
    __half2 r = __hmul2(*reinterpret_cast<__half2*>(&a), *reinterpret_cast<__half2*>(&b));
    return *reinterpret_cast<uint32_t*>(&r);
}

// corner k-offsets: b0 + 4*b1 + 16*b2
__device__ __constant__ int c_koff[8] = {0, 1, 4, 5, 16, 17, 20, 21};

// ---------------- prep ----------------
__global__ void prep_kernel(unsigned* __restrict__ out,
                            const float* __restrict__ x,
                            const float* __restrict__ w,
                            const float* __restrict__ root) {
    int i = blockIdx.x * 256 + threadIdx.x;
    if (i < N_NODES * 64) g_xh[i] = __float2half_rn(x[i]);
    if (i < (N_NODES + 1) * 64) g_agg[i] = 0.f;
    if (i < N_NODES)   g_cnt[i] = 0.f;
    if (i < 128)       g_stats[i] = 0.f;
    if (i < 32)        g_bcnt[i] = 0;
    if (i < NSEG * 64) out[i] = 0u;
    if (i < PADE) {
        g_rec[i] = make_float4(0.f, 0.f, 0.f, 0.f);
        g_rdst[i] = N_NODES;   // dump row
    }
    if (i < WTC * 64) {
        int col = i >> 6, c = i & 63;
        float v;
        if (col < 4096) {
            int k = col >> 6, d = col & 63;
            v = w[k * 4096 + c * 64 + d];
        } else {
            v = root[c * 64 + (col - 4096)];
        }
        g_wt[i] = __float2half_rn(v);
    }
}

__global__ void cnt_kernel(const int* __restrict__ eidx) {
    int e = blockIdx.x * 256 + threadIdx.x;
    if (e < N_EDGES) red_add_f32(&g_cnt[eidx[N_EDGES + e]], 1.f);
}

// ---------------- bucket sort by dense group id (27 groups) ----------------
__device__ __forceinline__ int edge_group(const float* attr, int e,
                                          float& t0, float& t1, float& t2) {
    float f0 = attr[e * 3 + 0] * 3.f;
    float f1 = attr[e * 3 + 1] * 3.f;
    float f2 = attr[e * 3 + 2] * 3.f;
    float l0 = fminf(fmaxf(floorf(f0), 0.f), 2.f);
    float l1 = fminf(fmaxf(floorf(f1), 0.f), 2.f);
    float l2 = fminf(fmaxf(floorf(f2), 0.f), 2.f);
    t0 = f0 - l0; t1 = f1 - l1; t2 = f2 - l2;
    return (int)l0 + 3 * (int)l1 + 9 * (int)l2;
}

__global__ void hist_kernel(const float* __restrict__ attr) {
    __shared__ int sc[NGRP];
    int t = threadIdx.x;
    if (t < NGRP) sc[t] = 0;
    __syncthreads();
    int e = blockIdx.x * 256 + t;
    if (e < N_EDGES) {
        float a, b, c;
        atomicAdd(&sc[edge_group(attr, e, a, b, c)], 1);
    }
    __syncthreads();
    if (t < NGRP && sc[t]) atomicAdd(&g_bcnt[t], sc[t]);
}

__global__ void scan_kernel() {
    if (threadIdx.x == 0) {
        int acc = 0;
        for (int g = 0; g < NGRP; g++) {
            g_boff[g] = acc;
            acc += ((g_bcnt[g] + 127) >> 7) << 7;
        }
        g_boff[NGRP] = acc;
    }
    if (threadIdx.x < 32) g_bfill[threadIdx.x] = 0;
}

__global__ void scatter_kernel(const int* __restrict__ eidx,
                               const float* __restrict__ attr) {
    __shared__ int sc[NGRP], sbase[NGRP], spos[NGRP];
    int t = threadIdx.x;
    if (t < NGRP) { sc[t] = 0; spos[t] = 0; }
    __syncthreads();
    int e = blockIdx.x * 256 + t;
    float t0 = 0.f, t1 = 0.f, t2 = 0.f;
    int g = -1;
    if (e < N_EDGES) {
        g = edge_group(attr, e, t0, t1, t2);
        atomicAdd(&sc[g], 1);
    }
    __syncthreads();
    if (t < NGRP && sc[t]) sbase[t] = atomicAdd(&g_bfill[t], sc[t]);
    __syncthreads();
    if (e < N_EDGES) {
        int p = g_boff[g] + sbase[g] + atomicAdd(&spos[g], 1);
        g_rec[p] = make_float4(t0, t1, t2, __uint_as_float((unsigned)eidx[e]));
        g_rdst[p] = eidx[N_EDGES + e];
    }
}

// ---------------- fused SplineConv: per 128-edge block, 8 corner GEMMs ----------------
// smem layout (dynamic):
#define SM_W    0                         // 8 * 64 * 72 halves = 73728 B (reused as fp32 C stage)
#define SM_X    73728                     // 128 * 72 halves = 18432 B
#define SM_BAS  92160                     // 8 * 128 floats = 4096 B
#define SM_DST  96256                     // 128 ints
#define SM_SRC  96768                     // 128 ints
#define SM_OFF  97280                     // 28 ints
#define SM_FUSED_TOTAL 97408
#define CSTRIDE 66                        // fp32 C stage stride

__global__ void __launch_bounds__(256, 2) spline_kernel() {
    extern __shared__ char sm[];
    __half* sW  = reinterpret_cast<__half*>(sm + SM_W);
    __half* sX  = reinterpret_cast<__half*>(sm + SM_X);
    float*  sBas = reinterpret_cast<float*>(sm + SM_BAS);
    int*    sDst = reinterpret_cast<int*>(sm + SM_DST);
    int*    sSrc = reinterpret_cast<int*>(sm + SM_SRC);
    int*    sOff = reinterpret_cast<int*>(sm + SM_OFF);

    const int t = threadIdx.x;
    const int e0 = blockIdx.x * 128;

    if (t < NGRP + 1) sOff[t] = g_boff[t];
    // load edge records
    if (t < 128) {
        float4 r = g_rec[e0 + t];
        sSrc[t] = (int)(__float_as_uint(r.w) & 0xFFFFFu);
        sDst[t] = g_rdst[e0 + t];
        float t0 = r.x, t1 = r.y, t2 = r.z;
        float s0 = 1.f - t0, s1 = 1.f - t1, s2 = 1.f - t2;
        #pragma unroll
        for (int b = 0; b < 8; b++) {
            float wb = ((b & 1) ? t0 : s0) * ((b & 2) ? t1 : s1) * ((b & 4) ? t2 : s2);
            sBas[b * 128 + t] = wb;
        }
    }
    __syncthreads();
    if (e0 >= sOff[NGRP]) return;

    int gi = 0;
    while (gi < NGRP - 1 && sOff[gi + 1] <= e0) gi++;
    const int l0 = gi % 3, l1 = (gi / 3) % 3, l2 = gi / 9;
    const int base_k = l0 + 4 * l1 + 16 * l2;

    const uint32_t sXb = smem_u32(sX);
    const uint32_t sWb = smem_u32(sW);

    // gather X rows (scaled later in registers): 1024 quads
    #pragma unroll
    for (int i = 0; i < 4; i++) {
        int f = t + i * 256;
        int row = f >> 3;
        int c8 = (f & 7) * 8;
        cp_async16(sXb + (row * 72 + c8) * 2,
                   g_xh + (long long)sSrc[row] * 64 + c8, 16);
    }
    // load 8 W matrices: 4096 quads
    #pragma unroll
    for (int i = 0; i < 16; i++) {
        int f = t + i * 256;
        int corner = f >> 9;
        int rem = f & 511;
        int j = rem >> 3;
        int c8 = (rem & 7) * 8;
        int kb = base_k + c_koff[corner];
        cp_async16(sWb + (corner * 64 * 72 + j * 72 + c8) * 2,
                   g_wt + ((long long)kb * 64 + j) * 64 + c8, 16);
    }
    CP_COMMIT();
    CP_WAIT0();
    __syncthreads();

    const int warp = t >> 5, lane = t & 31;
    const int wm = (warp & 3) * 32;          // 4 warps along M (128 edges)
    const int wn = (warp >> 2) * 32;         // 2 warps along N (64 cols)
    const int g = lane >> 2, tg = lane & 3;

    const int a_row = lane & 15, a_kc = (lane >> 4) * 8;
    const int b_row = (lane & 7) + (lane >> 4) * 8;
    const int b_kc  = ((lane >> 3) & 1) * 8;

    // cache A fragments (unscaled) for all 4 k-steps
    uint32_t A[4][2][4];
    #pragma unroll
    for (int ks = 0; ks < 4; ks++)
        #pragma unroll
        for (int mf = 0; mf < 2; mf++)
            ldsm_x4(A[ks][mf], sXb + ((wm + mf * 16 + a_row) * 72 + ks * 16 + a_kc) * 2);

    float acc[2][4][4];
    #pragma unroll
    for (int mf = 0; mf < 2; mf++)
        #pragma unroll
        for (int nf = 0; nf < 4; nf++)
            #pragma unroll
            for (int q = 0; q < 4; q++) acc[mf][nf][q] = 0.f;

    #pragma unroll
    for (int b = 0; b < 8; b++) {
        // per-row basis as duplicated half2 (rows: wm + mf*16 + {g, g+8})
        uint32_t hb[2][2];
        #pragma unroll
        for (int mf = 0; mf < 2; mf++) {
            __half2 h0 = __float2half2_rn(sBas[b * 128 + wm + mf * 16 + g]);
            __half2 h1 = __float2half2_rn(sBas[b * 128 + wm + mf * 16 + g + 8]);
            hb[mf][0] = *reinterpret_cast<uint32_t*>(&h0);
            hb[mf][1] = *reinterpret_cast<uint32_t*>(&h1);
        }
        const uint32_t wbase = sWb + b * 64 * 72 * 2;
        #pragma unroll
        for (int ks = 0; ks < 4; ks++) {
            uint32_t as[2][4];
            #pragma unroll
            for (int mf = 0; mf < 2; mf++) {
                as[mf][0] = hmul2u(A[ks][mf][0], hb[mf][0]);
                as[mf][1] = hmul2u(A[ks][mf][1], hb[mf][1]);
                as[mf][2] = hmul2u(A[ks][mf][2], hb[mf][0]);
                as[mf][3] = hmul2u(A[ks][mf][3], hb[mf][1]);
            }
            #pragma unroll
            for (int ns = 0; ns < 2; ns++) {
                uint32_t br[4];
                ldsm_x4(br, wbase + ((wn + ns * 16 + b_row) * 72 + ks * 16 + b_kc) * 2);
                uint32_t bf0[2] = {br[0], br[1]};
                uint32_t bf1[2] = {br[2], br[3]};
                hmma16816(acc[0][2 * ns],     as[0], bf0);
                hmma16816(acc[1][2 * ns],     as[1], bf0);
                hmma16816(acc[0][2 * ns + 1], as[0], bf1);
                hmma16816(acc[1][2 * ns + 1], as[1], bf1);
            }
        }
    }

    // stage C (fp32) into sW region, then coalesced v4 red to g_agg
    __syncthreads();
    float* sC = reinterpret_cast<float*>(sm + SM_W);   // 128 * 66 * 4 = 33792 B
    #pragma unroll
    for (int mf = 0; mf < 2; mf++) {
        #pragma unroll
        for (int nf = 0; nf < 4; nf++) {
            int c = wn + nf * 8 + 2 * tg;
            int r0 = wm + mf * 16 + g;
            *reinterpret_cast<float2*>(&sC[r0 * CSTRIDE + c]) =
                make_float2(acc[mf][nf][0], acc[mf][nf][1]);
            *reinterpret_cast<float2*>(&sC[(r0 + 8) * CSTRIDE + c]) =
                make_float2(acc[mf][nf][2], acc[mf][nf][3]);
        }
    }
    __syncthreads();
    #pragma unroll
    for (int i = 0; i < 8; i++) {
        int f = t + i * 256;            // 2048 v4 segments
        int row = f >> 4;
        int q4 = (f & 15) * 4;
        const float* cp = &sC[row * CSTRIDE + q4];
        float* ap = g_agg + (long long)sDst[row] * 64 + q4;
        red_add_v4(ap, cp[0], cp[1], cp[2], cp[3]);
    }
}

// ---------------- root GEMM: g_xr[m, d] = sum_c xh[m,c] * root[c,d] ----------------
__global__ void __launch_bounds__(256) root_kernel() {
    __shared__ __half sX[128 * 72];
    __shared__ __half sB[64 * 72];

    const int t = threadIdx.x;
    const int m0 = blockIdx.x * 128;
    const uint32_t sXb = smem_u32(sX);
    const uint32_t sBb = smem_u32(sB);

    #pragma unroll
    for (int i = 0; i < 4; i++) {
        int f = t + i * 256;
        int m = f >> 3;
        int c8 = (f & 7) * 8;
        cp_async16(sXb + (m * 72 + c8) * 2,
                   g_xh + (long long)(m0 + m) * 64 + c8,
                   (m0 + m < N_NODES) ? 16 : 0);
    }
    #pragma unroll
    for (int i = 0; i < 2; i++) {
        int f = t + i * 256;
        int j = f >> 3;
        int c8 = (f & 7) * 8;
        cp_async16(sBb + (j * 72 + c8) * 2,
                   g_wt + ((long long)4096 + j) * 64 + c8, 16);
    }
    CP_COMMIT();
    CP_WAIT0();
    __syncthreads();

    const int warp = t >> 5, lane = t & 31;
    const int wm = (warp & 3) * 32;
    const int wn = (warp >> 2) * 32;
    const int g = lane >> 2, tg = lane & 3;
    const int a_row = lane & 15, a_kc = (lane >> 4) * 8;
    const int b_row = (lane & 7) + (lane >> 4) * 8;
    const int b_kc  = ((lane >> 3) & 1) * 8;

    float acc[2][4][4];
    #pragma unroll
    for (int mf = 0; mf < 2; mf++)
        #pragma unroll
        for (int nf = 0; nf < 4; nf++)
            #pragma unroll
            for (int q = 0; q < 4; q++) acc[mf][nf][q] = 0.f;

    #pragma unroll
    for (int ks = 0; ks < 4; ks++) {
        uint32_t a[2][4];
        #pragma unroll
        for (int mf = 0; mf < 2; mf++)
            ldsm_x4(a[mf], sXb + ((wm + mf * 16 + a_row) * 72 + ks * 16 + a_kc) * 2);
        #pragma unroll
        for (int ns = 0; ns < 2; ns++) {
            uint32_t br[4];
            ldsm_x4(br, sBb + ((wn + ns * 16 + b_row) * 72 + ks * 16 + b_kc) * 2);
            uint32_t bf0[2] = {br[0], br[1]};
            uint32_t bf1[2] = {br[2], br[3]};
            hmma16816(acc[0][2 * ns],     a[0], bf0);
            hmma16816(acc[1][2 * ns],     a[1], bf0);
            hmma16816(acc[0][2 * ns + 1], a[0], bf1);
            hmma16816(acc[1][2 * ns + 1], a[1], bf1);
        }
    }

    #pragma unroll
    for (int mf = 0; mf < 2; mf++) {
        int r0 = m0 + wm + mf * 16 + g;
        #pragma unroll
        for (int nf = 0; nf < 4; nf++) {
            int c = wn + nf * 8 + 2 * tg;
            if (r0 < N_NODES)
                *reinterpret_cast<float2*>(&g_xr[(long long)r0 * 64 + c]) =
                    make_float2(acc[mf][nf][0], acc[mf][nf][1]);
            if (r0 + 8 < N_NODES)
                *reinterpret_cast<float2*>(&g_xr[(long long)(r0 + 8) * 64 + c]) =
                    make_float2(acc[mf][nf][2], acc[mf][nf][3]);
        }
    }
}

// ---------------- node kernel: h = ELU(agg/cnt + xr + bias), stats, fused max-pool ----
__global__ void __launch_bounds__(256) node_kernel(const float* __restrict__ bias,
                                                   const float* __restrict__ pos,
                                                   const int* __restrict__ batch,
                                                   unsigned* __restrict__ outp) {
    __shared__ float sred[128];
    int t = threadIdx.x;
    if (t < 128) sred[t] = 0.f;
    __syncthreads();

    int lane = t & 31, warp = t >> 5;
    int gw = blockIdx.x * 8 + warp;
    int nw = gridDim.x * 8;
    int d0 = lane, d1 = lane + 32;
    float b0 = bias[d0], b1 = bias[d1];
    float su0 = 0.f, sq0 = 0.f, su1 = 0.f, sq1 = 0.f;

    for (int n = gw; n < N_NODES; n += nw) {
        float ic = 1.f / fmaxf(g_cnt[n], 1.f);
        long long off = (long long)n * 64;
        float a0 = g_agg[off + d0] * ic + b0 + g_xr[off + d0];
        float a1 = g_agg[off + d1] * ic + b1 + g_xr[off + d1];
        float h0 = a0 > 0.f ? a0 : expm1f(a0);
        float h1 = a1 > 0.f ? a1 : expm1f(a1);
        su0 += h0; sq0 += h0 * h0;
        su1 += h1; sq1 += h1 * h1;
        float p0 = pos[n * 3 + 0], p1 = pos[n * 3 + 1], p2 = pos[n * 3 + 2];
        int v0 = min(max((int)floorf(p0 * (1.f / 32.f)), 0), 7);
        int v1 = min(max((int)floorf(p1 * (1.f / 32.f)), 0), 7);
        int v2 = min(max((int)floorf(p2 * (1.f / 32.f)), 0), 7);
        int cl = batch[n] * 512 + v0 * 64 + v1 * 8 + v2;
        unsigned* op = outp + (long long)cl * 64;
        atomicMax(op + d0, encf(h0));
        atomicMax(op + d1, encf(h1));
    }
    atomicAdd(&sred[d0], su0);
    atomicAdd(&sred[d1], su1);
    atomicAdd(&sred[64 + d0], sq0);
    atomicAdd(&sred[64 + d1], sq1);
    __syncthreads();
    if (t < 128) atomicAdd(&g_stats[t], sred[t]);
}

// ---------------- decode: BN finalize + apply affine to pooled maxima ----------
__global__ void decode_kernel(float* __restrict__ out,
                              const float* __restrict__ gamma,
                              const float* __restrict__ beta) {
    __shared__ float ssc[64], ssh[64];
    int t = threadIdx.x;
    if (t < 64) {
        float mean = g_stats[t] * (1.f / N_NODES);
        float var  = g_stats[64 + t] * (1.f / N_NODES) - mean * mean;
        float inv  = rsqrtf(var + EPS_BN);
        float sc   = gamma[t] * inv;
        ssc[t] = sc;
        ssh[t] = beta[t] - mean * sc;
    }
    __syncthreads();
    int i = blockIdx.x * 256 + t;
    if (i < NSEG * 64) {
        int d = i & 63;
        unsigned u = reinterpret_cast<unsigned*>(out)[i];
        out[i] = u ? (ssc[d] * decf(u) + ssh[d]) : 0.f;
    }
}

// ---------------- launch ----------------
extern "C" void kernel_launch(void* const* d_in, const int* in_sizes, int n_in,
                              void* d_out, int out_size) {
    const float* x      = (const float*)d_in[0];
    const int*   eidx   = (const int*)  d_in[1];
    const float* attr   = (const float*)d_in[2];
    const float* pos    = (const float*)d_in[3];
    const int*   batch  = (const int*)  d_in[4];
    const float* weight = (const float*)d_in[5];
    const float* root   = (const float*)d_in[6];
    const float* bias   = (const float*)d_in[7];
    const float* gamma  = (const float*)d_in[8];
    const float* beta   = (const float*)d_in[9];

    cudaFuncSetAttribute(spline_kernel, cudaFuncAttributeMaxDynamicSharedMemorySize,
                         SM_FUSED_TOTAL);

    prep_kernel<<<12500, 256>>>((unsigned*)d_out, x, weight, root);
    hist_kernel<<<(N_EDGES + 255) / 256, 256>>>(attr);
    scan_kernel<<<1, 32>>>();
    scatter_kernel<<<(N_EDGES + 255) / 256, 256>>>(eidx, attr);
    cnt_kernel<<<(N_EDGES + 255) / 256, 256>>>(eidx);

    root_kernel<<<(N_NODES + 127) / 128, 256>>>();
    spline_kernel<<<NBLK, 256, SM_FUSED_TOTAL>>>();

    node_kernel<<<800, 256>>>(bias, pos, batch, (unsigned*)d_out);
    decode_kernel<<<(NSEG * 64 + 255) / 256, 256>>>((float*)d_out, gamma, beta);
}

// round 15
// speedup vs baseline: 1.6444x; 1.0473x over previous
#include <cuda_runtime.h>
#include <cuda_fp16.h>
#include <math.h>
#include <cstdint>

#define N_NODES 50000
#define N_EDGES 800000
#define NGRP    27
#define PADE    (N_EDGES + NGRP * 128)   // 803456
#define NBLK    (PADE / 128)             // 6277
#define WTC     4160                     // 4096 spline cols + 64 root cols
#define NSEG    8192
#define EPS_BN  1e-5f

// ---------------- device scratch ----------------
__device__ __half g_xh[N_NODES * 64];            // x fp16
__device__ __half g_wt[WTC * 64];                // [col][cin] fp16 (spline + root)
__device__ __half g_xr[N_NODES * 64];            // x @ root (fp16)
__device__ float  g_agg[(N_NODES + 1) * 64];     // +1 dump row for pad edges
__device__ float  g_cnt[N_NODES];
__device__ float  g_stats[128];
__device__ float4 g_rec[PADE];                   // t0,t1,t2, bits(src)
__device__ int    g_rdst[PADE];
__device__ int    g_bcnt[32];
__device__ int    g_boff[32];                    // padded exclusive offsets, [27]=total
__device__ int    g_bfill[32];

// ---------------- helpers ----------------
__device__ __forceinline__ unsigned encf(float f) {
    unsigned u = __float_as_uint(f);
    return (u & 0x80000000u) ? ~u : (u | 0x80000000u);
}
__device__ __forceinline__ float decf(unsigned e) {
    return __uint_as_float((e & 0x80000000u) ? (e ^ 0x80000000u) : ~e);
}
__device__ __forceinline__ void red_add_v4(float* p, float a, float b, float c, float d) {
    asm volatile("red.global.add.v4.f32 [%0], {%1, %2, %3, %4};"
                 :: "l"(p), "f"(a), "f"(b), "f"(c), "f"(d) : "memory");
}
__device__ __forceinline__ void red_add_f32(float* p, float a) {
    asm volatile("red.global.add.f32 [%0], %1;" :: "l"(p), "f"(a) : "memory");
}
__device__ __forceinline__ void hmma16816(float* d, const uint32_t* a, const uint32_t* b) {
    asm volatile(
        "mma.sync.aligned.m16n8k16.row.col.f32.f16.f16.f32 "
        "{%0,%1,%2,%3}, {%4,%5,%6,%7}, {%8,%9}, {%0,%1,%2,%3};"
        : "+f"(d[0]), "+f"(d[1]), "+f"(d[2]), "+f"(d[3])
        : "r"(a[0]), "r"(a[1]), "r"(a[2]), "r"(a[3]), "r"(b[0]), "r"(b[1]));
}
__device__ __forceinline__ void ldsm_x4(uint32_t* r, uint32_t addr) {
    asm volatile("ldmatrix.sync.aligned.m8n8.x4.shared.b16 {%0,%1,%2,%3}, [%4];"
                 : "=r"(r[0]), "=r"(r[1]), "=r"(r[2]), "=r"(r[3]) : "r"(addr));
}
__device__ __forceinline__ uint32_t smem_u32(const void* p) {
    uint32_t a;
    asm("{ .reg .u64 t; cvta.to.shared.u64 t, %1; cvt.u32.u64 %0, t; }" : "=r"(a) : "l"(p));
    return a;
}
__device__ __forceinline__ void cp_async16(uint32_t dst, const void* src, int src_bytes) {
    asm volatile("cp.async.cg.shared.global [%0], [%1], 16, %2;"
                 :: "r"(dst), "l"(src), "r"(src_bytes) : "memory");
}
#define CP_COMMIT() asm volatile("cp.async.commit_group;" ::: "memory")
#define CP_WAIT0()  asm volatile("cp.async.wait_group 0;" ::: "memory")
__device__ __forceinline__ uint32_t hmul2u(uint32_t a, uint32_t b) {
    __half2 r = __hmul2(*reinterpret_cast<__half2*>(&a), *reinterpret_cast<__half2*>(&b));
    return *reinterpret_cast<uint32_t*>(&r);
}

// corner k-offsets: b0 + 4*b1 + 16*b2
__device__ __constant__ int c_koff[8] = {0, 1, 4, 5, 16, 17, 20, 21};

__device__ __forceinline__ int edge_group(const float* attr, int e,
                                          float& t0, float& t1, float& t2) {
    float f0 = attr[e * 3 + 0] * 3.f;
    float f1 = attr[e * 3 + 1] * 3.f;
    float f2 = attr[e * 3 + 2] * 3.f;
    float l0 = fminf(fmaxf(floorf(f0), 0.f), 2.f);
    float l1 = fminf(fmaxf(floorf(f1), 0.f), 2.f);
    float l2 = fminf(fmaxf(floorf(f2), 0.f), 2.f);
    t0 = f0 - l0; t1 = f1 - l1; t2 = f2 - l2;
    return (int)l0 + 3 * (int)l1 + 9 * (int)l2;
}

// ---------------- prep: zeros + conversions + group histogram (fused) ----------------
__global__ void prep_kernel(unsigned* __restrict__ out,
                            const float* __restrict__ x,
                            const float* __restrict__ w,
                            const float* __restrict__ root,
                            const float* __restrict__ attr) {
    __shared__ int sc[NGRP];
    int t = threadIdx.x;
    if (t < NGRP) sc[t] = 0;
    __syncthreads();

    int i = blockIdx.x * 256 + t;
    if (i < N_NODES * 64) g_xh[i] = __float2half_rn(x[i]);
    if (i < (N_NODES + 1) * 64) g_agg[i] = 0.f;
    if (i < N_NODES)   g_cnt[i] = 0.f;
    if (i < 128)       g_stats[i] = 0.f;
    if (i < 32)        g_bcnt[i] = 0;
    if (i < NSEG * 64) out[i] = 0u;
    if (i < PADE) {
        g_rec[i] = make_float4(0.f, 0.f, 0.f, 0.f);
        g_rdst[i] = N_NODES;   // dump row
    }
    if (i < WTC * 64) {
        int col = i >> 6, c = i & 63;
        float v;
        if (col < 4096) {
            int k = col >> 6, d = col & 63;
            v = w[k * 4096 + c * 64 + d];
        } else {
            v = root[c * 64 + (col - 4096)];
        }
        g_wt[i] = __float2half_rn(v);
    }
    if (i < N_EDGES) {
        float a, b, c;
        atomicAdd(&sc[edge_group(attr, i, a, b, c)], 1);
    }
    __syncthreads();
    if (t < NGRP && sc[t]) atomicAdd(&g_bcnt[t], sc[t]);
}

__global__ void scan_kernel() {
    if (threadIdx.x == 0) {
        int acc = 0;
        for (int g = 0; g < NGRP; g++) {
            g_boff[g] = acc;
            acc += ((g_bcnt[g] + 127) >> 7) << 7;
        }
        g_boff[NGRP] = acc;
    }
    if (threadIdx.x < 32) g_bfill[threadIdx.x] = 0;
}

// ---------------- scatter + degree count (fused) ----------------
__global__ void scatter_kernel(const int* __restrict__ eidx,
                               const float* __restrict__ attr) {
    __shared__ int sc[NGRP], sbase[NGRP], spos[NGRP];
    int t = threadIdx.x;
    if (t < NGRP) { sc[t] = 0; spos[t] = 0; }
    __syncthreads();
    int e = blockIdx.x * 256 + t;
    float t0 = 0.f, t1 = 0.f, t2 = 0.f;
    int g = -1, d = 0;
    if (e < N_EDGES) {
        g = edge_group(attr, e, t0, t1, t2);
        d = eidx[N_EDGES + e];
        atomicAdd(&sc[g], 1);
    }
    __syncthreads();
    if (t < NGRP && sc[t]) sbase[t] = atomicAdd(&g_bfill[t], sc[t]);
    __syncthreads();
    if (e < N_EDGES) {
        int p = g_boff[g] + sbase[g] + atomicAdd(&spos[g], 1);
        g_rec[p] = make_float4(t0, t1, t2, __uint_as_float((unsigned)eidx[e]));
        g_rdst[p] = d;
        red_add_f32(&g_cnt[d], 1.f);
    }
}

// ---------------- fused SplineConv: per 128-edge block, 8 corner GEMMs ----------------
#define SM_W    0                         // 8 * 64 * 72 halves = 73728 B (reused as fp32 C stage)
#define SM_X    73728                     // 128 * 72 halves = 18432 B
#define SM_BAS  92160                     // 8 * 128 floats = 4096 B
#define SM_DST  96256                     // 128 ints
#define SM_SRC  96768                     // 128 ints
#define SM_OFF  97280                     // 28 ints
#define SM_FUSED_TOTAL 97408
#define CSTRIDE 66                        // fp32 C stage stride

__global__ void __launch_bounds__(256, 2) spline_kernel() {
    extern __shared__ char sm[];
    __half* sX  = reinterpret_cast<__half*>(sm + SM_X);
    float*  sBas = reinterpret_cast<float*>(sm + SM_BAS);
    int*    sDst = reinterpret_cast<int*>(sm + SM_DST);
    int*    sSrc = reinterpret_cast<int*>(sm + SM_SRC);
    int*    sOff = reinterpret_cast<int*>(sm + SM_OFF);

    const int t = threadIdx.x;
    const int e0 = blockIdx.x * 128;

    if (t < NGRP + 1) sOff[t] = g_boff[t];
    if (t < 128) {
        float4 r = g_rec[e0 + t];
        sSrc[t] = (int)(__float_as_uint(r.w) & 0xFFFFFu);
        sDst[t] = g_rdst[e0 + t];
        float t0 = r.x, t1 = r.y, t2 = r.z;
        float s0 = 1.f - t0, s1 = 1.f - t1, s2 = 1.f - t2;
        #pragma unroll
        for (int b = 0; b < 8; b++) {
            float wb = ((b & 1) ? t0 : s0) * ((b & 2) ? t1 : s1) * ((b & 4) ? t2 : s2);
            sBas[b * 128 + t] = wb;
        }
    }
    __syncthreads();
    if (e0 >= sOff[NGRP]) return;

    int gi = 0;
    while (gi < NGRP - 1 && sOff[gi + 1] <= e0) gi++;
    const int l0 = gi % 3, l1 = (gi / 3) % 3, l2 = gi / 9;
    const int base_k = l0 + 4 * l1 + 16 * l2;

    const uint32_t sXb = smem_u32(sX);
    const uint32_t sWb = smem_u32(sm + SM_W);

    #pragma unroll
    for (int i = 0; i < 4; i++) {
        int f = t + i * 256;
        int row = f >> 3;
        int c8 = (f & 7) * 8;
        cp_async16(sXb + (row * 72 + c8) * 2,
                   g_xh + (long long)sSrc[row] * 64 + c8, 16);
    }
    #pragma unroll
    for (int i = 0; i < 16; i++) {
        int f = t + i * 256;
        int corner = f >> 9;
        int rem = f & 511;
        int j = rem >> 3;
        int c8 = (rem & 7) * 8;
        int kb = base_k + c_koff[corner];
        cp_async16(sWb + (corner * 64 * 72 + j * 72 + c8) * 2,
                   g_wt + ((long long)kb * 64 + j) * 64 + c8, 16);
    }
    CP_COMMIT();
    CP_WAIT0();
    __syncthreads();

    const int warp = t >> 5, lane = t & 31;
    const int wm = (warp & 3) * 32;
    const int wn = (warp >> 2) * 32;
    const int g = lane >> 2, tg = lane & 3;

    const int a_row = lane & 15, a_kc = (lane >> 4) * 8;
    const int b_row = (lane & 7) + (lane >> 4) * 8;
    const int b_kc  = ((lane >> 3) & 1) * 8;

    uint32_t A[4][2][4];
    #pragma unroll
    for (int ks = 0; ks < 4; ks++)
        #pragma unroll
        for (int mf = 0; mf < 2; mf++)
            ldsm_x4(A[ks][mf], sXb + ((wm + mf * 16 + a_row) * 72 + ks * 16 + a_kc) * 2);

    float acc[2][4][4];
    #pragma unroll
    for (int mf = 0; mf < 2; mf++)
        #pragma unroll
        for (int nf = 0; nf < 4; nf++)
            #pragma unroll
            for (int q = 0; q < 4; q++) acc[mf][nf][q] = 0.f;

    #pragma unroll
    for (int b = 0; b < 8; b++) {
        uint32_t hb[2][2];
        #pragma unroll
        for (int mf = 0; mf < 2; mf++) {
            __half2 h0 = __float2half2_rn(sBas[b * 128 + wm + mf * 16 + g]);
            __half2 h1 = __float2half2_rn(sBas[b * 128 + wm + mf * 16 + g + 8]);
            hb[mf][0] = *reinterpret_cast<uint32_t*>(&h0);
            hb[mf][1] = *reinterpret_cast<uint32_t*>(&h1);
        }
        const uint32_t wbase = sWb + b * 64 * 72 * 2;
        #pragma unroll
        for (int ks = 0; ks < 4; ks++) {
            uint32_t as[2][4];
            #pragma unroll
            for (int mf = 0; mf < 2; mf++) {
                as[mf][0] = hmul2u(A[ks][mf][0], hb[mf][0]);
                as[mf][1] = hmul2u(A[ks][mf][1], hb[mf][1]);
                as[mf][2] = hmul2u(A[ks][mf][2], hb[mf][0]);
                as[mf][3] = hmul2u(A[ks][mf][3], hb[mf][1]);
            }
            #pragma unroll
            for (int ns = 0; ns < 2; ns++) {
                uint32_t br[4];
                ldsm_x4(br, wbase + ((wn + ns * 16 + b_row) * 72 + ks * 16 + b_kc) * 2);
                uint32_t bf0[2] = {br[0], br[1]};
                uint32_t bf1[2] = {br[2], br[3]};
                hmma16816(acc[0][2 * ns],     as[0], bf0);
                hmma16816(acc[1][2 * ns],     as[1], bf0);
                hmma16816(acc[0][2 * ns + 1], as[0], bf1);
                hmma16816(acc[1][2 * ns + 1], as[1], bf1);
            }
        }
    }

    __syncthreads();
    float* sC = reinterpret_cast<float*>(sm + SM_W);
    #pragma unroll
    for (int mf = 0; mf < 2; mf++) {
        #pragma unroll
        for (int nf = 0; nf < 4; nf++) {
            int c = wn + nf * 8 + 2 * tg;
            int r0 = wm + mf * 16 + g;
            *reinterpret_cast<float2*>(&sC[r0 * CSTRIDE + c]) =
                make_float2(acc[mf][nf][0], acc[mf][nf][1]);
            *reinterpret_cast<float2*>(&sC[(r0 + 8) * CSTRIDE + c]) =
                make_float2(acc[mf][nf][2], acc[mf][nf][3]);
        }
    }
    __syncthreads();
    #pragma unroll
    for (int i = 0; i < 8; i++) {
        int f = t + i * 256;
        int row = f >> 4;
        int q4 = (f & 15) * 4;
        const float* cp = &sC[row * CSTRIDE + q4];
        float* ap = g_agg + (long long)sDst[row] * 64 + q4;
        red_add_v4(ap, cp[0], cp[1], cp[2], cp[3]);
    }
}

// ---------------- root GEMM: g_xr[m, d] = sum_c xh[m,c] * root[c,d] (fp16 out) -------
__global__ void __launch_bounds__(256) root_kernel() {
    __shared__ __half sX[128 * 72];
    __shared__ __half sB[64 * 72];

    const int t = threadIdx.x;
    const int m0 = blockIdx.x * 128;
    const uint32_t sXb = smem_u32(sX);
    const uint32_t sBb = smem_u32(sB);

    #pragma unroll
    for (int i = 0; i < 4; i++) {
        int f = t + i * 256;
        int m = f >> 3;
        int c8 = (f & 7) * 8;
        cp_async16(sXb + (m * 72 + c8) * 2,
                   g_xh + (long long)(m0 + m) * 64 + c8,
                   (m0 + m < N_NODES) ? 16 : 0);
    }
    #pragma unroll
    for (int i = 0; i < 2; i++) {
        int f = t + i * 256;
        int j = f >> 3;
        int c8 = (f & 7) * 8;
        cp_async16(sBb + (j * 72 + c8) * 2,
                   g_wt + ((long long)4096 + j) * 64 + c8, 16);
    }
    CP_COMMIT();
    CP_WAIT0();
    __syncthreads();

    const int warp = t >> 5, lane = t & 31;
    const int wm = (warp & 3) * 32;
    const int wn = (warp >> 2) * 32;
    const int g = lane >> 2, tg = lane & 3;
    const int a_row = lane & 15, a_kc = (lane >> 4) * 8;
    const int b_row = (lane & 7) + (lane >> 4) * 8;
    const int b_kc  = ((lane >> 3) & 1) * 8;

    float acc[2][4][4];
    #pragma unroll
    for (int mf = 0; mf < 2; mf++)
        #pragma unroll
        for (int nf = 0; nf < 4; nf++)
            #pragma unroll
            for (int q = 0; q < 4; q++) acc[mf][nf][q] = 0.f;

    #pragma unroll
    for (int ks = 0; ks < 4; ks++) {
        uint32_t a[2][4];
        #pragma unroll
        for (int mf = 0; mf < 2; mf++)
            ldsm_x4(a[mf], sXb + ((wm + mf * 16 + a_row) * 72 + ks * 16 + a_kc) * 2);
        #pragma unroll
        for (int ns = 0; ns < 2; ns++) {
            uint32_t br[4];
            ldsm_x4(br, sBb + ((wn + ns * 16 + b_row) * 72 + ks * 16 + b_kc) * 2);
            uint32_t bf0[2] = {br[0], br[1]};
            uint32_t bf1[2] = {br[2], br[3]};
            hmma16816(acc[0][2 * ns],     a[0], bf0);
            hmma16816(acc[1][2 * ns],     a[1], bf0);
            hmma16816(acc[0][2 * ns + 1], a[0], bf1);
            hmma16816(acc[1][2 * ns + 1], a[1], bf1);
        }
    }

    #pragma unroll
    for (int mf = 0; mf < 2; mf++) {
        int r0 = m0 + wm + mf * 16 + g;
        #pragma unroll
        for (int nf = 0; nf < 4; nf++) {
            int c = wn + nf * 8 + 2 * tg;
            if (r0 < N_NODES)
                *reinterpret_cast<__half2*>(&g_xr[(long long)r0 * 64 + c]) =
                    __floats2half2_rn(acc[mf][nf][0], acc[mf][nf][1]);
            if (r0 + 8 < N_NODES)
                *reinterpret_cast<__half2*>(&g_xr[(long long)(r0 + 8) * 64 + c]) =
                    __floats2half2_rn(acc[mf][nf][2], acc[mf][nf][3]);
        }
    }
}

// ---------------- node kernel: h = ELU(agg/cnt + xr + bias), stats, fused max-pool ----
__global__ void __launch_bounds__(256) node_kernel(const float* __restrict__ bias,
                                                   const float* __restrict__ pos,
                                                   const int* __restrict__ batch,
                                                   unsigned* __restrict__ outp) {
    __shared__ float sred[128];
    int t = threadIdx.x;
    if (t < 128) sred[t] = 0.f;
    __syncthreads();

    int lane = t & 31, warp = t >> 5;
    int gw = blockIdx.x * 8 + warp;
    int nw = gridDim.x * 8;
    int d0 = lane, d1 = lane + 32;
    float b0 = bias[d0], b1 = bias[d1];
    float su0 = 0.f, sq0 = 0.f, su1 = 0.f, sq1 = 0.f;

    for (int n = gw; n < N_NODES; n += nw) {
        float ic = 1.f / fmaxf(g_cnt[n], 1.f);
        long long off = (long long)n * 64;
        float a0 = g_agg[off + d0] * ic + b0 + __half2float(g_xr[off + d0]);
        float a1 = g_agg[off + d1] * ic + b1 + __half2float(g_xr[off + d1]);
        float h0 = a0 > 0.f ? a0 : expm1f(a0);
        float h1 = a1 > 0.f ? a1 : expm1f(a1);
        su0 += h0; sq0 += h0 * h0;
        su1 += h1; sq1 += h1 * h1;
        float p0 = pos[n * 3 + 0], p1 = pos[n * 3 + 1], p2 = pos[n * 3 + 2];
        int v0 = min(max((int)floorf(p0 * (1.f / 32.f)), 0), 7);
        int v1 = min(max((int)floorf(p1 * (1.f / 32.f)), 0), 7);
        int v2 = min(max((int)floorf(p2 * (1.f / 32.f)), 0), 7);
        int cl = batch[n] * 512 + v0 * 64 + v1 * 8 + v2;
        unsigned* op = outp + (long long)cl * 64;
        atomicMax(op + d0, encf(h0));
        atomicMax(op + d1, encf(h1));
    }
    atomicAdd(&sred[d0], su0);
    atomicAdd(&sred[d1], su1);
    atomicAdd(&sred[64 + d0], sq0);
    atomicAdd(&sred[64 + d1], sq1);
    __syncthreads();
    if (t < 128) atomicAdd(&g_stats[t], sred[t]);
}

// ---------------- decode: BN finalize + apply affine to pooled maxima ----------
__global__ void decode_kernel(float* __restrict__ out,
                              const float* __restrict__ gamma,
                              const float* __restrict__ beta) {
    __shared__ float ssc[64], ssh[64];
    int t = threadIdx.x;
    if (t < 64) {
        float mean = g_stats[t] * (1.f / N_NODES);
        float var  = g_stats[64 + t] * (1.f / N_NODES) - mean * mean;
        float inv  = rsqrtf(var + EPS_BN);
        float sc   = gamma[t] * inv;
        ssc[t] = sc;
        ssh[t] = beta[t] - mean * sc;
    }
    __syncthreads();
    int i = blockIdx.x * 256 + t;
    if (i < NSEG * 64) {
        int d = i & 63;
        unsigned u = reinterpret_cast<unsigned*>(out)[i];
        out[i] = u ? (ssc[d] * decf(u) + ssh[d]) : 0.f;
    }
}

// ---------------- launch ----------------
extern "C" void kernel_launch(void* const* d_in, const int* in_sizes, int n_in,
                              void* d_out, int out_size) {
    const float* x      = (const float*)d_in[0];
    const int*   eidx   = (const int*)  d_in[1];
    const float* attr   = (const float*)d_in[2];
    const float* pos    = (const float*)d_in[3];
    const int*   batch  = (const int*)  d_in[4];
    const float* weight = (const float*)d_in[5];
    const float* root   = (const float*)d_in[6];
    const float* bias   = (const float*)d_in[7];
    const float* gamma  = (const float*)d_in[8];
    const float* beta   = (const float*)d_in[9];

    cudaFuncSetAttribute(spline_kernel, cudaFuncAttributeMaxDynamicSharedMemorySize,
                         SM_FUSED_TOTAL);

    prep_kernel<<<12500, 256>>>((unsigned*)d_out, x, weight, root, attr);
    scan_kernel<<<1, 32>>>();
    scatter_kernel<<<(N_EDGES + 255) / 256, 256>>>(eidx, attr);

    root_kernel<<<(N_NODES + 127) / 128, 256>>>();
    spline_kernel<<<NBLK, 256, SM_FUSED_TOTAL>>>();

    node_kernel<<<800, 256>>>(bias, pos, batch, (unsigned*)d_out);
    decode_kernel<<<(NSEG * 64 + 255) / 256, 256>>>((float*)d_out, gamma, beta);
}